// round 1
// baseline (speedup 1.0000x reference)
#include <cuda_runtime.h>
#include <cuda_bf16.h>

// Problem constants (fixed by setup_inputs)
#define B_   16
#define G_   20000
#define D_   256
#define K_   2048
#define NTOK (K_ + 1)

// GEMM tiling
#define MT 32   // genes per block tile
#define KC 32   // k-chunk staged in smem

// Device scratch (no allocations allowed)
__device__ int   g_sel_idx[B_ * K_];
__device__ int   g_nsel[B_];
__device__ float g_w2t[D_ * D_];   // w2 transposed: w2t[d][e] = w2[e][d]

// ---------------------------------------------------------------------------
// Kernel A: per-batch exact top-K selection + ascending-index compaction.
// Key = (~bits(expr) << 32) | gene_idx  -> K smallest keys == top-K by
// (value desc, index asc), matching jax.lax.top_k tie-breaking. Keys unique.
// ---------------------------------------------------------------------------
__global__ __launch_bounds__(256) void select_kernel(const float* __restrict__ expr) {
    const int b = blockIdx.x;
    const float* ex = expr + (size_t)b * G_;
    const int t = threadIdx.x;

    __shared__ unsigned int hist[256];
    __shared__ unsigned long long s_pref;
    __shared__ int s_rem;

    if (t == 0) { s_pref = 0ULL; s_rem = K_; }
    __syncthreads();

    // 8-round MSB radix select (8 bits/round) for the K-th smallest key
    for (int round = 0; round < 8; ++round) {
        const int shift = 56 - 8 * round;
        hist[t] = 0;
        __syncthreads();
        const unsigned long long pref = s_pref;
        for (int g = t; g < G_; g += 256) {
            unsigned int bits = __float_as_uint(ex[g]);
            unsigned long long key = ((unsigned long long)(~bits) << 32) | (unsigned int)g;
            bool match = (round == 0) ||
                         ((key >> (shift + 8)) == (pref >> (shift + 8)));
            if (match)
                atomicAdd(&hist[(unsigned int)(key >> shift) & 255u], 1u);
        }
        __syncthreads();
        if (t == 0) {
            int rem = s_rem;
            unsigned int cum = 0;
            int d = 0;
            for (; d < 256; ++d) {
                if (cum + hist[d] >= (unsigned int)rem) break;
                cum += hist[d];
            }
            s_rem = rem - (int)cum;
            s_pref = s_pref | ((unsigned long long)d << shift);
        }
        __syncthreads();
    }
    const unsigned long long Tk = s_pref;  // K-th smallest key

    // Order-preserving compaction: contiguous per-thread ranges + block scan.
    const int chunk = (G_ + 255) / 256;
    const int start = t * chunk;
    const int end = min(start + chunk, G_);

    int cnt = 0;
    for (int g = start; g < end; ++g) {
        float v = ex[g];
        unsigned int bits = __float_as_uint(v);
        unsigned long long key = ((unsigned long long)(~bits) << 32) | (unsigned int)g;
        if (key <= Tk && v > 0.0f) cnt++;
    }

    __shared__ int scn[256];
    scn[t] = cnt;
    __syncthreads();
    for (int off = 1; off < 256; off <<= 1) {
        int v = (t >= off) ? scn[t - off] : 0;
        __syncthreads();
        scn[t] += v;
        __syncthreads();
    }
    int pos = scn[t] - cnt;
    for (int g = start; g < end; ++g) {
        float v = ex[g];
        unsigned int bits = __float_as_uint(v);
        unsigned long long key = ((unsigned long long)(~bits) << 32) | (unsigned int)g;
        if (key <= Tk && v > 0.0f) {
            g_sel_idx[b * K_ + pos] = g;
            pos++;
        }
    }
    if (t == 255) g_nsel[b] = scn[255];
}

// ---------------------------------------------------------------------------
// Kernel T: transpose w2[e][d] -> w2t[d][e] so the GEMM's smem staging is
// fully coalesced (k rows contiguous in e).
// ---------------------------------------------------------------------------
__global__ void transpose_w2_kernel(const float* __restrict__ w2) {
    __shared__ float tile[32][33];
    int x = blockIdx.x * 32 + threadIdx.x;  // d
    int y = blockIdx.y * 32 + threadIdx.y;  // e
#pragma unroll
    for (int i = 0; i < 32; i += 8)
        tile[threadIdx.y + i][threadIdx.x] = w2[(size_t)(y + i) * D_ + x];
    __syncthreads();
    int xt = blockIdx.y * 32 + threadIdx.x;  // e
    int yt = blockIdx.x * 32 + threadIdx.y;  // d
#pragma unroll
    for (int i = 0; i < 32; i += 8)
        g_w2t[(size_t)(yt + i) * D_ + xt] = tile[threadIdx.x][threadIdx.y + i];
}

// ---------------------------------------------------------------------------
// Kernel B: tokens for selected genes.
//   h[m][d] = gelu_exact(e_m * w1[d] + b1[d])     (computed into smem, [k][m])
//   out[b, 1+j, e] = sum_d h[d] * w2[e][d] + b2[e] + gene_emb[g][e]
// Block: 256 threads, tile = 32 genes x 256 outputs; per-thread 8x4 register
// tile. All smem operand reads are LDS.128 broadcast or phase-contiguous.
// ---------------------------------------------------------------------------
__global__ __launch_bounds__(256, 3) void tok_kernel(
    const float* __restrict__ expr, const float* __restrict__ gene_emb,
    const float* __restrict__ w1, const float* __restrict__ b1,
    const float* __restrict__ b2, float* __restrict__ out) {
    extern __shared__ float sm[];
    float* hs = sm;             // [D_][MT]  (k-major)  32 KB
    float* ws = sm + D_ * MT;   // [KC][D_]            32 KB
    __shared__ float se[MT];
    __shared__ int   sg[MT];

    const int b = blockIdx.y;
    const int j0 = blockIdx.x * MT;
    const int t = threadIdx.x;

    if (t < MT) {
        int ns = g_nsel[b];
        int j = j0 + t;
        if (j < ns) {
            int g = g_sel_idx[b * K_ + j];
            sg[t] = g;
            se[t] = expr[(size_t)b * G_ + g];
        } else {
            sg[t] = -1;
            se[t] = 0.0f;
        }
    }
    __syncthreads();

    // Compute h tile: thread t covers m = t&31, d in [(t>>5)*32, +32)
    {
        const int m = t & (MT - 1);
        const int d0 = (t >> 5) * 32;
        const float e = se[m];
#pragma unroll 8
        for (int dd = 0; dd < 32; ++dd) {
            int d = d0 + dd;
            float x = fmaf(e, __ldg(&w1[d]), __ldg(&b1[d]));
            float hv = 0.5f * x * (1.0f + erff(x * 0.70710678118654752f));
            hs[d * MT + m] = hv;   // lanes write consecutive m -> conflict-free
        }
    }

    const int tn = t & 63;  const int n0 = tn << 2;   // 4 outputs in e
    const int tm = t >> 6;  const int m0 = tm << 3;   // 8 genes

    float acc[8][4];
#pragma unroll
    for (int i = 0; i < 8; ++i)
#pragma unroll
        for (int j2 = 0; j2 < 4; ++j2) acc[i][j2] = 0.0f;

    for (int kc = 0; kc < D_; kc += KC) {
        __syncthreads();
        // Stage w2t chunk [KC][D_]: fully coalesced float4 copy
        {
            const float4* src = (const float4*)(g_w2t + (size_t)kc * D_);
            float4* dst = (float4*)ws;
#pragma unroll
            for (int i = 0; i < (KC * D_ / 4) / 256; ++i)
                dst[t + i * 256] = src[t + i * 256];
        }
        __syncthreads();

#pragma unroll 8
        for (int kk = 0; kk < KC; ++kk) {
            const int k = kc + kk;
            float4 w  = *(const float4*)(ws + kk * D_ + n0);
            float4 h0 = *(const float4*)(hs + k * MT + m0);
            float4 h1 = *(const float4*)(hs + k * MT + m0 + 4);
            float hv[8] = {h0.x, h0.y, h0.z, h0.w, h1.x, h1.y, h1.z, h1.w};
#pragma unroll
            for (int mi = 0; mi < 8; ++mi) {
                acc[mi][0] = fmaf(hv[mi], w.x, acc[mi][0]);
                acc[mi][1] = fmaf(hv[mi], w.y, acc[mi][1]);
                acc[mi][2] = fmaf(hv[mi], w.z, acc[mi][2]);
                acc[mi][3] = fmaf(hv[mi], w.w, acc[mi][3]);
            }
        }
    }

    // Epilogue: + b2 + gene_emb, zero invalid slots. Slot 0 is CLS (kernel C).
    const float4 bb = *(const float4*)(b2 + n0);
#pragma unroll
    for (int mi = 0; mi < 8; ++mi) {
        const int mrow = m0 + mi;
        const int g = sg[mrow];
        const int j = j0 + mrow;
        float4 r;
        if (g >= 0) {
            float4 ge = *(const float4*)(gene_emb + (size_t)g * D_ + n0);
            r.x = acc[mi][0] + bb.x + ge.x;
            r.y = acc[mi][1] + bb.y + ge.y;
            r.z = acc[mi][2] + bb.z + ge.z;
            r.w = acc[mi][3] + bb.w + ge.w;
        } else {
            r = make_float4(0.0f, 0.0f, 0.0f, 0.0f);
        }
        size_t off = ((size_t)b * NTOK + 1 + j) * D_ + n0;
        *(float4*)(out + off) = r;
    }
}

// ---------------------------------------------------------------------------
// Kernel C: CLS token rows + mask (mask written only if out_size covers it).
// ---------------------------------------------------------------------------
__global__ void cls_mask_kernel(const float* __restrict__ cls,
                                float* __restrict__ out, long long out_size) {
    long long i = (long long)blockIdx.x * blockDim.x + threadIdx.x;
    const long long clsN = (long long)B_ * D_;
    if (i < clsN) {
        int b = (int)(i / D_);
        int d = (int)(i % D_);
        out[(long long)b * NTOK * D_ + d] = cls[d];
    }
    const long long TOK = (long long)B_ * NTOK * D_;
    const long long maskN = (long long)B_ * NTOK;
    if (out_size >= TOK + maskN && i < maskN) {
        int b = (int)(i / NTOK);
        int s = (int)(i % NTOK);
        float v = (s == 0) ? 1.0f : ((s - 1) < g_nsel[b] ? 1.0f : 0.0f);
        out[TOK + i] = v;
    }
}

// ---------------------------------------------------------------------------
extern "C" void kernel_launch(void* const* d_in, const int* in_sizes, int n_in,
                              void* d_out, int out_size) {
    const float* expr     = (const float*)d_in[0];
    const float* gene_emb = (const float*)d_in[1];
    const float* w1       = (const float*)d_in[2];
    const float* b1       = (const float*)d_in[3];
    const float* w2       = (const float*)d_in[4];
    const float* b2       = (const float*)d_in[5];
    const float* cls      = (const float*)d_in[6];
    float* out = (float*)d_out;

    const int smem_bytes = (D_ * MT + KC * D_) * (int)sizeof(float);  // 64 KB
    cudaFuncSetAttribute(tok_kernel, cudaFuncAttributeMaxDynamicSharedMemorySize,
                         smem_bytes);

    select_kernel<<<B_, 256>>>(expr);
    transpose_w2_kernel<<<dim3(8, 8), dim3(32, 8)>>>(w2);
    tok_kernel<<<dim3(K_ / MT, B_), 256, smem_bytes>>>(expr, gene_emb, w1, b1, b2, out);

    int total_cm = B_ * NTOK;  // 32784 covers B_*D_ = 4096 too
    cls_mask_kernel<<<(total_cm + 255) / 256, 256>>>(cls, out, (long long)out_size);
}

// round 6
// speedup vs baseline: 1.2819x; 1.2819x over previous
#include <cuda_runtime.h>
#include <cuda_bf16.h>
#include <cstdint>

// Problem constants (fixed by setup_inputs)
#define B_   16
#define G_   20000
#define D_   256
#define K_   2048
#define NTOK (K_ + 1)

// GEMM tiling
#define MT   128   // block tile M (genes)
#define NT   128   // block tile N (output dims); two n-halves via blockIdx.y
#define KC   32    // K chunk
#define SH   36    // hs row stride (floats): bank = 4g+t -> conflict-free A frags
#define SB   136   // bs row stride (floats): bank = 8t+g -> conflict-free B frags

// Device scratch
__device__ int g_sel_idx[B_ * K_];
__device__ int g_nsel[B_];

__device__ __forceinline__ uint32_t f2tf32(float x) {
    uint32_t r;
    asm("cvt.rna.tf32.f32 %0, %1;" : "=r"(r) : "f"(x));
    return r;
}

__device__ __forceinline__ void mma_tf32(float& c0, float& c1, float& c2, float& c3,
                                         uint32_t a0, uint32_t a1, uint32_t a2, uint32_t a3,
                                         uint32_t b0, uint32_t b1) {
    asm volatile(
        "mma.sync.aligned.m16n8k8.row.col.f32.tf32.tf32.f32 "
        "{%0,%1,%2,%3}, {%4,%5,%6,%7}, {%8,%9}, {%0,%1,%2,%3};"
        : "+f"(c0), "+f"(c1), "+f"(c2), "+f"(c3)
        : "r"(a0), "r"(a1), "r"(a2), "r"(a3), "r"(b0), "r"(b1));
}

// ---------------------------------------------------------------------------
// Kernel A: per-batch exact top-K selection + compaction + CLS row + mask.
// Key = (~bits(expr) << 32) | gene_idx -> K smallest == jax top_k semantics.
// ---------------------------------------------------------------------------
__global__ __launch_bounds__(256) void select_kernel(const float* __restrict__ expr,
                                                     const float* __restrict__ cls,
                                                     float* __restrict__ out,
                                                     long long out_size) {
    const int b = blockIdx.x;
    const float* ex = expr + (size_t)b * G_;
    const int t = threadIdx.x;

    __shared__ unsigned int hist[256];
    __shared__ unsigned long long s_pref;
    __shared__ int s_rem;

    if (t == 0) { s_pref = 0ULL; s_rem = K_; }
    __syncthreads();

    for (int round = 0; round < 8; ++round) {
        const int shift = 56 - 8 * round;
        hist[t] = 0;
        __syncthreads();
        const unsigned long long pref = s_pref;
        for (int g = t; g < G_; g += 256) {
            unsigned int bits = __float_as_uint(ex[g]);
            unsigned long long key = ((unsigned long long)(~bits) << 32) | (unsigned int)g;
            bool match = (round == 0) ||
                         ((key >> (shift + 8)) == (pref >> (shift + 8)));
            if (match)
                atomicAdd(&hist[(unsigned int)(key >> shift) & 255u], 1u);
        }
        __syncthreads();
        if (t == 0) {
            int rem = s_rem;
            unsigned int cum = 0;
            int d = 0;
            for (; d < 256; ++d) {
                if (cum + hist[d] >= (unsigned int)rem) break;
                cum += hist[d];
            }
            s_rem = rem - (int)cum;
            s_pref = s_pref | ((unsigned long long)d << shift);
        }
        __syncthreads();
    }
    const unsigned long long Tk = s_pref;

    const int chunk = (G_ + 255) / 256;
    const int start = t * chunk;
    const int end = min(start + chunk, G_);

    int cnt = 0;
    for (int g = start; g < end; ++g) {
        float v = ex[g];
        unsigned int bits = __float_as_uint(v);
        unsigned long long key = ((unsigned long long)(~bits) << 32) | (unsigned int)g;
        if (key <= Tk && v > 0.0f) cnt++;
    }

    __shared__ int scn[256];
    scn[t] = cnt;
    __syncthreads();
    for (int off = 1; off < 256; off <<= 1) {
        int v = (t >= off) ? scn[t - off] : 0;
        __syncthreads();
        scn[t] += v;
        __syncthreads();
    }
    int pos = scn[t] - cnt;
    for (int g = start; g < end; ++g) {
        float v = ex[g];
        unsigned int bits = __float_as_uint(v);
        unsigned long long key = ((unsigned long long)(~bits) << 32) | (unsigned int)g;
        if (key <= Tk && v > 0.0f) {
            g_sel_idx[b * K_ + pos] = g;
            pos++;
        }
    }
    if (t == 255) g_nsel[b] = scn[255];
    __syncthreads();
    const int ns = scn[255];

    // CLS row
    if (t < D_) out[(size_t)b * NTOK * D_ + t] = cls[t];
    // mask (only if out buffer includes it)
    const long long TOK = (long long)B_ * NTOK * D_;
    if (out_size >= TOK + (long long)B_ * NTOK) {
        for (int s = t; s < NTOK; s += 256) {
            float v = (s == 0) ? 1.0f : (((s - 1) < ns) ? 1.0f : 0.0f);
            out[TOK + (long long)b * NTOK + s] = v;
        }
    }
}

// ---------------------------------------------------------------------------
// Kernel B: fused gelu + tf32 mma.sync GEMM + epilogue.
//   out[b, 1+j, n] = sum_k gelu(e_j*w1[k]+b1[k]) * w2[n][k] + b2[n] + ge[g][n]
// Block 256 threads = 8 warps (4 m-groups x 2 n-groups).
// Warp tile 32x64: 2 m16 x 8 n8 fragments, 64 fp32 accums/thread.
// ---------------------------------------------------------------------------
__global__ __launch_bounds__(256, 2) void tok_mma_kernel(
    const float* __restrict__ expr, const float* __restrict__ gene_emb,
    const float* __restrict__ w1, const float* __restrict__ b1,
    const float* __restrict__ w2, const float* __restrict__ b2,
    float* __restrict__ out) {
    __shared__ uint32_t hs[MT * SH];   // h tile chunk [m][k], tf32 bits
    __shared__ uint32_t bs[KC * SB];   // w2 chunk transposed [k][n], tf32 bits
    __shared__ float se[MT];
    __shared__ int   sg[MT];

    const int tid  = threadIdx.x;
    const int lane = tid & 31;
    const int warp = tid >> 5;
    const int gq   = lane >> 2;   // groupID 0..7
    const int tq   = lane & 3;    // threadID-in-group 0..3
    const int wm   = warp & 3;    // m warp group
    const int wn   = warp >> 2;   // n warp group

    const int b    = blockIdx.z;
    const int j0   = blockIdx.x * MT;
    const int nblk = blockIdx.y * NT;

    // Prologue: gather selected genes for this tile
    if (tid < MT) {
        const int ns = g_nsel[b];
        const int j = j0 + tid;
        if (j < ns) {
            int g = g_sel_idx[b * K_ + j];
            sg[tid] = g;
            se[tid] = expr[(size_t)b * G_ + g];
        } else {
            sg[tid] = -1;
            se[tid] = 0.0f;
        }
    }
    __syncthreads();

    float acc[2][8][4];
#pragma unroll
    for (int mi = 0; mi < 2; ++mi)
#pragma unroll
        for (int ni = 0; ni < 8; ++ni)
#pragma unroll
            for (int q = 0; q < 4; ++q) acc[mi][ni][q] = 0.0f;

    // staging maps
    const int sm_m  = tid >> 1;          // h: row
    const int sm_kh = (tid & 1) << 4;    // h: k half (0/16)
    const float e_m = se[sm_m];
    const int sb_n  = tid & 127;         // b: col
    const int sb_kh = (tid >> 7) << 4;   // b: k half (0/16)
    const float* w2row = w2 + (size_t)(nblk + sb_n) * D_;

    for (int kc = 0; kc < D_; kc += KC) {
        __syncthreads();   // previous chunk's smem reads done

        // stage h chunk: 16 gelu evals per thread
#pragma unroll 4
        for (int jj = 0; jj < 16; ++jj) {
            const int k = kc + sm_kh + jj;
            float x = fmaf(e_m, __ldg(&w1[k]), __ldg(&b1[k]));
            float hv = 0.5f * x * (1.0f + erff(x * 0.70710678118654752f));
            hs[sm_m * SH + sm_kh + jj] = f2tf32(hv);
        }
        // stage w2 chunk transposed: 4 float4 loads -> 16 scalar stores
#pragma unroll
        for (int q = 0; q < 4; ++q) {
            const float4 v = __ldg((const float4*)(w2row + kc + sb_kh) + q);
            const int kb = sb_kh + 4 * q;
            bs[(kb + 0) * SB + sb_n] = f2tf32(v.x);
            bs[(kb + 1) * SB + sb_n] = f2tf32(v.y);
            bs[(kb + 2) * SB + sb_n] = f2tf32(v.z);
            bs[(kb + 3) * SB + sb_n] = f2tf32(v.w);
        }
        __syncthreads();

        // 4 k-steps of m16n8k8
#pragma unroll
        for (int ks = 0; ks < 4; ++ks) {
            const int k8 = ks * 8;
            uint32_t a[2][4];
#pragma unroll
            for (int mi = 0; mi < 2; ++mi) {
                const int rm = wm * 32 + mi * 16;
                a[mi][0] = hs[(rm + gq) * SH + k8 + tq];
                a[mi][1] = hs[(rm + 8 + gq) * SH + k8 + tq];
                a[mi][2] = hs[(rm + gq) * SH + k8 + tq + 4];
                a[mi][3] = hs[(rm + 8 + gq) * SH + k8 + tq + 4];
            }
#pragma unroll
            for (int ni = 0; ni < 8; ++ni) {
                const int nc = wn * 64 + ni * 8 + gq;
                const uint32_t b0 = bs[(k8 + tq) * SB + nc];
                const uint32_t b1r = bs[(k8 + tq + 4) * SB + nc];
#pragma unroll
                for (int mi = 0; mi < 2; ++mi)
                    mma_tf32(acc[mi][ni][0], acc[mi][ni][1], acc[mi][ni][2], acc[mi][ni][3],
                             a[mi][0], a[mi][1], a[mi][2], a[mi][3], b0, b1r);
            }
        }
    }

    // Epilogue: + b2 + gene_emb, zero invalid rows. Cols for this thread:
    // n = nblk + wn*64 + ni*8 + 2*tq (+1)
    float2 bb[8];
#pragma unroll
    for (int ni = 0; ni < 8; ++ni)
        bb[ni] = __ldg((const float2*)(b2 + nblk + wn * 64 + ni * 8 + 2 * tq));

#pragma unroll
    for (int mi = 0; mi < 2; ++mi) {
#pragma unroll
        for (int rr = 0; rr < 2; ++rr) {
            const int r = wm * 32 + mi * 16 + rr * 8 + gq;
            const int g = sg[r];
            float* orow = out + ((size_t)b * NTOK + 1 + j0 + r) * D_ + nblk;
            if (g >= 0) {
                const float* gerow = gene_emb + (size_t)g * D_ + nblk;
#pragma unroll
                for (int ni = 0; ni < 8; ++ni) {
                    const int col = wn * 64 + ni * 8 + 2 * tq;
                    const float2 ge = __ldg((const float2*)(gerow + col));
                    float2 rv;
                    rv.x = acc[mi][ni][2 * rr + 0] + bb[ni].x + ge.x;
                    rv.y = acc[mi][ni][2 * rr + 1] + bb[ni].y + ge.y;
                    *(float2*)(orow + col) = rv;
                }
            } else {
                const float2 z = make_float2(0.f, 0.f);
#pragma unroll
                for (int ni = 0; ni < 8; ++ni) {
                    const int col = wn * 64 + ni * 8 + 2 * tq;
                    *(float2*)(orow + col) = z;
                }
            }
        }
    }
}

// ---------------------------------------------------------------------------
extern "C" void kernel_launch(void* const* d_in, const int* in_sizes, int n_in,
                              void* d_out, int out_size) {
    const float* expr     = (const float*)d_in[0];
    const float* gene_emb = (const float*)d_in[1];
    const float* w1       = (const float*)d_in[2];
    const float* b1       = (const float*)d_in[3];
    const float* w2       = (const float*)d_in[4];
    const float* b2       = (const float*)d_in[5];
    const float* cls      = (const float*)d_in[6];
    float* out = (float*)d_out;

    select_kernel<<<B_, 256>>>(expr, cls, out, (long long)out_size);
    tok_mma_kernel<<<dim3(K_ / MT, D_ / NT, B_), 256>>>(expr, gene_emb, w1, b1,
                                                        w2, b2, out);
}

// round 7
// speedup vs baseline: 1.6036x; 1.2510x over previous
#include <cuda_runtime.h>
#include <cuda_bf16.h>
#include <cstdint>

// Problem constants (fixed by setup_inputs)
#define B_   16
#define G_   20000
#define D_   256
#define K_   2048
#define NTOK (K_ + 1)

// GEMM tiling
#define MT   128   // block tile M (genes)
#define NT   256   // block tile N (full output dim)
#define KC   32    // K chunk
#define SH   36    // hs row stride: A-frag bank = 4*gq+tq -> conflict-free
#define SB2  264   // bs row stride: B-frag bank = 8*tq+gq -> conflict-free

// Select kernel
#define SEL_T 1024
#define CH    20   // ceil(G_/SEL_T)

// Device scratch
__device__ int g_sel_idx[B_ * K_];
__device__ int g_nsel[B_];

__device__ __forceinline__ uint32_t f2tf32(float x) {
    uint32_t r;
    asm("cvt.rna.tf32.f32 %0, %1;" : "=r"(r) : "f"(x));
    return r;
}

__device__ __forceinline__ void mma_tf32(float& c0, float& c1, float& c2, float& c3,
                                         uint32_t a0, uint32_t a1, uint32_t a2, uint32_t a3,
                                         uint32_t b0, uint32_t b1) {
    asm volatile(
        "mma.sync.aligned.m16n8k8.row.col.f32.tf32.tf32.f32 "
        "{%0,%1,%2,%3}, {%4,%5,%6,%7}, {%8,%9}, {%0,%1,%2,%3};"
        : "+f"(c0), "+f"(c1), "+f"(c2), "+f"(c3)
        : "r"(a0), "r"(a1), "r"(a2), "r"(a3), "r"(b0), "r"(b1));
}

// ---------------------------------------------------------------------------
// Kernel A: per-batch exact top-K selection + compaction + CLS row + mask.
// 32-bit key = ~bits(expr); ties broken by gene index via explicit tie-rank
// (exactly jax.lax.top_k semantics: value desc, index asc). Values live in
// registers; histogram atomics aggregated per-warp via match_any.
// ---------------------------------------------------------------------------
__global__ __launch_bounds__(SEL_T) void select_kernel(const float* __restrict__ expr,
                                                       const float* __restrict__ cls,
                                                       float* __restrict__ out,
                                                       long long out_size) {
    const int b = blockIdx.x;
    const float* ex = expr + (size_t)b * G_;
    const int t = threadIdx.x;
    const int lane = t & 31;
    const int start = t * CH;

    float v[CH];
#pragma unroll
    for (int i = 0; i < CH; ++i) {
        const int g = start + i;
        v[i] = (g < G_) ? ex[g] : 0.0f;
    }

    __shared__ unsigned int h[256], c[256];
    __shared__ unsigned int s_pref;
    __shared__ int s_rem;
    __shared__ int scn[SEL_T];

    if (t == 0) { s_pref = 0u; s_rem = K_; }
    __syncthreads();

    // 4 radix-256 rounds over the 32-bit key
    for (int round = 0; round < 4; ++round) {
        const int shift = 24 - 8 * round;
        if (t < 256) h[t] = 0;
        __syncthreads();
        const unsigned int pref = s_pref;
        const int rem = s_rem;
#pragma unroll
        for (int i = 0; i < CH; ++i) {
            const int g = start + i;
            const unsigned int key = ~__float_as_uint(v[i]);
            bool valid = (g < G_);
            if (round > 0) valid = valid && (((key ^ pref) >> (shift + 8)) == 0);
            const unsigned int bucket = valid ? ((key >> shift) & 255u) : 0x10000u;
            const unsigned int mask = __match_any_sync(0xFFFFFFFFu, bucket);
            const int leader = __ffs(mask) - 1;
            if (valid && lane == leader) atomicAdd(&h[bucket], __popc(mask));
        }
        __syncthreads();
        if (t < 256) c[t] = h[t];
        __syncthreads();
        // inclusive scan over 256 bins
        for (int off = 1; off < 256; off <<= 1) {
            unsigned int add = 0;
            if (t < 256 && t >= off) add = c[t - off];
            __syncthreads();
            if (t < 256) c[t] += add;
            __syncthreads();
        }
        if (t < 256) {
            const unsigned int excl = c[t] - h[t];
            if ((int)excl < rem && rem <= (int)c[t]) {
                s_pref = pref | (t << shift);
                s_rem = rem - (int)excl;
            }
        }
        __syncthreads();
    }
    const unsigned int T = s_pref;   // exact key of K-th smallest
    const int r = s_rem;             // ties (key==T) to keep, smallest indices
    const float tval = __uint_as_float(~T);
    const bool tie_pos = (tval > 0.0f);

    // Pass 1: per-thread counts
    int cnt_less = 0, cnt_tie = 0;
#pragma unroll
    for (int i = 0; i < CH; ++i) {
        const int g = start + i;
        if (g < G_) {
            const unsigned int key = ~__float_as_uint(v[i]);
            if (key < T) { if (v[i] > 0.0f) cnt_less++; }
            else if (key == T) cnt_tie++;
        }
    }

    // Scan ties
    scn[t] = cnt_tie;
    __syncthreads();
    for (int off = 1; off < SEL_T; off <<= 1) {
        int add = (t >= off) ? scn[t - off] : 0;
        __syncthreads();
        scn[t] += add;
        __syncthreads();
    }
    const int tie_excl = scn[t] - cnt_tie;

    // kept ties in this thread
    int kept_ties = r - tie_excl;
    if (kept_ties < 0) kept_ties = 0;
    if (kept_ties > cnt_tie) kept_ties = cnt_tie;
    if (!tie_pos) kept_ties = 0;
    const int cnt_keep = cnt_less + kept_ties;

    // Scan keeps
    __syncthreads();
    scn[t] = cnt_keep;
    __syncthreads();
    for (int off = 1; off < SEL_T; off <<= 1) {
        int add = (t >= off) ? scn[t - off] : 0;
        __syncthreads();
        scn[t] += add;
        __syncthreads();
    }
    int pos = scn[t] - cnt_keep;
    const int ns = scn[SEL_T - 1];

    // Pass 2: write kept gene indices in ascending order
    int tie_seen = tie_excl;
#pragma unroll
    for (int i = 0; i < CH; ++i) {
        const int g = start + i;
        if (g < G_) {
            const unsigned int key = ~__float_as_uint(v[i]);
            if (key < T) {
                if (v[i] > 0.0f) g_sel_idx[b * K_ + (pos++)] = g;
            } else if (key == T) {
                if (tie_seen < r && tie_pos) g_sel_idx[b * K_ + (pos++)] = g;
                tie_seen++;
            }
        }
    }
    if (t == 0) g_nsel[b] = ns;

    // CLS row + mask
    if (t < D_) out[(size_t)b * NTOK * D_ + t] = cls[t];
    const long long TOK = (long long)B_ * NTOK * D_;
    if (out_size >= TOK + (long long)B_ * NTOK) {
        for (int s = t; s < NTOK; s += SEL_T) {
            float m = (s == 0) ? 1.0f : (((s - 1) < ns) ? 1.0f : 0.0f);
            out[TOK + (long long)b * NTOK + s] = m;
        }
    }
}

// ---------------------------------------------------------------------------
// Kernel B: fused gelu + tf32 mma.sync GEMM + epilogue, full N per block.
// 512 threads = 16 warps (4 m-groups x 4 n-groups), warp tile 32x64.
// w2 chunks register-prefetched one iteration ahead to hide L2 latency.
// ---------------------------------------------------------------------------
__global__ __launch_bounds__(512, 1) void tok_mma_kernel(
    const float* __restrict__ expr, const float* __restrict__ gene_emb,
    const float* __restrict__ w1, const float* __restrict__ b1,
    const float* __restrict__ w2, const float* __restrict__ b2,
    float* __restrict__ out) {
    extern __shared__ uint32_t dynsm[];
    uint32_t* hs = dynsm;              // [MT][SH]  h chunk, tf32 bits
    uint32_t* bs = dynsm + MT * SH;    // [KC][SB2] w2 chunk transposed, tf32 bits
    __shared__ float se[MT];
    __shared__ int   sg[MT];

    const int tid  = threadIdx.x;
    const int lane = tid & 31;
    const int warp = tid >> 5;
    const int gq   = lane >> 2;   // 0..7
    const int tq   = lane & 3;    // 0..3
    const int wm   = warp & 3;    // m warp group
    const int wn   = warp >> 2;   // n warp group

    const int b  = blockIdx.y;
    const int j0 = blockIdx.x * MT;

    // Prologue: gather selected genes
    if (tid < MT) {
        const int ns = g_nsel[b];
        const int j = j0 + tid;
        if (j < ns) {
            int g = g_sel_idx[b * K_ + tid + j0];
            sg[tid] = g;
            se[tid] = expr[(size_t)b * G_ + g];
        } else {
            sg[tid] = -1;
            se[tid] = 0.0f;
        }
    }
    __syncthreads();

    float acc[2][8][4];
#pragma unroll
    for (int mi = 0; mi < 2; ++mi)
#pragma unroll
        for (int ni = 0; ni < 8; ++ni)
#pragma unroll
            for (int q = 0; q < 4; ++q) acc[mi][ni][q] = 0.0f;

    // staging maps
    const int sm_m = tid >> 2;            // h: gene row 0..127
    const int smk  = (tid & 3) << 3;      // h: k offset within chunk (0/8/16/24)
    const float e_m = se[sm_m];
    const int sb_n  = tid & 255;          // b: output col
    const int sb_kh = (tid >> 8) << 4;    // b: k half (0/16)
    const float* w2row = w2 + (size_t)sb_n * D_;

    // prefetch chunk 0 of w2
    float4 pw[4];
#pragma unroll
    for (int q = 0; q < 4; ++q)
        pw[q] = __ldg((const float4*)(w2row + sb_kh) + q);

    for (int kc = 0; kc < D_; kc += KC) {
        // gelu for this chunk (w1/b1 L1-hot)
        float hv[8];
        {
            const float4 w1a = __ldg((const float4*)(w1 + kc + smk));
            const float4 w1b = __ldg((const float4*)(w1 + kc + smk) + 1);
            const float4 b1a = __ldg((const float4*)(b1 + kc + smk));
            const float4 b1b = __ldg((const float4*)(b1 + kc + smk) + 1);
            const float wv[8] = {w1a.x, w1a.y, w1a.z, w1a.w, w1b.x, w1b.y, w1b.z, w1b.w};
            const float bv[8] = {b1a.x, b1a.y, b1a.z, b1a.w, b1b.x, b1b.y, b1b.z, b1b.w};
#pragma unroll
            for (int j = 0; j < 8; ++j) {
                float x = fmaf(e_m, wv[j], bv[j]);
                hv[j] = 0.5f * x * (1.0f + erff(x * 0.70710678118654752f));
            }
        }
        __syncthreads();   // previous chunk's smem reads done

        // store staged w2 chunk (transpose to [k][n]) and h chunk
#pragma unroll
        for (int q = 0; q < 4; ++q) {
            const int kb = sb_kh + 4 * q;
            bs[(kb + 0) * SB2 + sb_n] = f2tf32(pw[q].x);
            bs[(kb + 1) * SB2 + sb_n] = f2tf32(pw[q].y);
            bs[(kb + 2) * SB2 + sb_n] = f2tf32(pw[q].z);
            bs[(kb + 3) * SB2 + sb_n] = f2tf32(pw[q].w);
        }
#pragma unroll
        for (int j = 0; j < 8; ++j)
            hs[sm_m * SH + smk + j] = f2tf32(hv[j]);

        // prefetch next chunk (overlaps with MMA below)
        if (kc + KC < D_) {
#pragma unroll
            for (int q = 0; q < 4; ++q)
                pw[q] = __ldg((const float4*)(w2row + kc + KC + sb_kh) + q);
        }
        __syncthreads();

        // 4 k-steps of m16n8k8
#pragma unroll
        for (int ks = 0; ks < 4; ++ks) {
            const int k8 = ks * 8;
            uint32_t a[2][4];
#pragma unroll
            for (int mi = 0; mi < 2; ++mi) {
                const int rm = wm * 32 + mi * 16;
                a[mi][0] = hs[(rm + gq) * SH + k8 + tq];
                a[mi][1] = hs[(rm + 8 + gq) * SH + k8 + tq];
                a[mi][2] = hs[(rm + gq) * SH + k8 + tq + 4];
                a[mi][3] = hs[(rm + 8 + gq) * SH + k8 + tq + 4];
            }
#pragma unroll
            for (int ni = 0; ni < 8; ++ni) {
                const int nc = wn * 64 + ni * 8 + gq;
                const uint32_t b0 = bs[(k8 + tq) * SB2 + nc];
                const uint32_t b1r = bs[(k8 + tq + 4) * SB2 + nc];
#pragma unroll
                for (int mi = 0; mi < 2; ++mi)
                    mma_tf32(acc[mi][ni][0], acc[mi][ni][1], acc[mi][ni][2], acc[mi][ni][3],
                             a[mi][0], a[mi][1], a[mi][2], a[mi][3], b0, b1r);
            }
        }
    }

    // Epilogue: + b2 + gene_emb, zero invalid rows.
    float2 bb[8];
#pragma unroll
    for (int ni = 0; ni < 8; ++ni)
        bb[ni] = __ldg((const float2*)(b2 + wn * 64 + ni * 8 + 2 * tq));

#pragma unroll
    for (int mi = 0; mi < 2; ++mi) {
#pragma unroll
        for (int rr = 0; rr < 2; ++rr) {
            const int rrow = wm * 32 + mi * 16 + rr * 8 + gq;
            const int g = sg[rrow];
            float* orow = out + ((size_t)b * NTOK + 1 + j0 + rrow) * D_;
            if (g >= 0) {
                const float* gerow = gene_emb + (size_t)g * D_;
#pragma unroll
                for (int ni = 0; ni < 8; ++ni) {
                    const int col = wn * 64 + ni * 8 + 2 * tq;
                    const float2 ge = __ldg((const float2*)(gerow + col));
                    float2 rv;
                    rv.x = acc[mi][ni][2 * rr + 0] + bb[ni].x + ge.x;
                    rv.y = acc[mi][ni][2 * rr + 1] + bb[ni].y + ge.y;
                    *(float2*)(orow + col) = rv;
                }
            } else {
                const float2 z = make_float2(0.f, 0.f);
#pragma unroll
                for (int ni = 0; ni < 8; ++ni) {
                    const int col = wn * 64 + ni * 8 + 2 * tq;
                    *(float2*)(orow + col) = z;
                }
            }
        }
    }
}

// ---------------------------------------------------------------------------
extern "C" void kernel_launch(void* const* d_in, const int* in_sizes, int n_in,
                              void* d_out, int out_size) {
    const float* expr     = (const float*)d_in[0];
    const float* gene_emb = (const float*)d_in[1];
    const float* w1       = (const float*)d_in[2];
    const float* b1       = (const float*)d_in[3];
    const float* w2       = (const float*)d_in[4];
    const float* b2       = (const float*)d_in[5];
    const float* cls      = (const float*)d_in[6];
    float* out = (float*)d_out;

    const int smem_bytes = (MT * SH + KC * SB2) * (int)sizeof(uint32_t);  // ~52 KB
    cudaFuncSetAttribute(tok_mma_kernel, cudaFuncAttributeMaxDynamicSharedMemorySize,
                         smem_bytes);

    select_kernel<<<B_, SEL_T>>>(expr, cls, out, (long long)out_size);
    tok_mma_kernel<<<dim3(K_ / MT, B_), 512, smem_bytes>>>(expr, gene_emb, w1, b1,
                                                           w2, b2, out);
}